// round 11
// baseline (speedup 1.0000x reference)
#include <cuda_runtime.h>
#include <cstddef>

// Problem constants: B=1, F=12, C=128, H=W=256, pad=1.
#define H_IN 256
#define W_IN 256
#define CH   128
#define H_OUT 258
#define W_OUT 258
#define PLANE_IN  (H_IN * W_IN)     // 65536
#define PLANE_OUT (H_OUT * W_OUT)   // 66564
#define N_PLANES  (12 * CH)         // 1536
// 8 floats per thread -> 8192 threads per plane -> 32 per row
#define N_COPY_BLOCKS ((N_PLANES * PLANE_IN / 8) / 256)   // 49152
#define N_CORNER_BLOCKS 24          // 6144 threads: one per (plane, corner)

// ---------------------------------------------------------------------------
// Single launch, block-granularity fusion (R9 structure, proven).
// Copy path now does 2x LDG.128 per thread (MLP_p1=2) to cut exposed DRAM
// latency; R9 showed DRAM=71.6%, issue=27%, L1=44% -> latency-bound with
// MLP_p1=1. Edge scatter identical in structure, extended to 8 cols/thread.
// ---------------------------------------------------------------------------
__global__ void hp_main(const float* __restrict__ in, float* __restrict__ out) {
    // ================= corner blocks =================
    if (blockIdx.x >= N_COPY_BLOCKS) {
        int t = (blockIdx.x - N_COPY_BLOCKS) * blockDim.x + threadIdx.x;
        if (t >= N_PLANES * 4) return;
        const int corner = t & 3;          // 0=TL 1=TR 2=BL 3=BR
        const int plane  = t >> 2;

        const int face = plane >> 7;
        const int ch   = plane & (CH - 1);
        const int grp  = face >> 2;
        const int fi   = face & 3;
        const int A  = (fi + 1) & 3;
        const int B2 = (fi + 2) & 3;
        const int D  = (fi + 3) & 3;
        const int LAST = H_IN - 1;

        auto ibase = [&](int g) -> const float* {
            return in + ((size_t)g * CH + ch) * PLANE_IN;
        };

        float v;
        if (grp == 0) {
            switch (corner) {
                case 0:  v = ibase(B2)[0];     break;
                case 1:  v = ibase(A)[0];      break;
                case 2:  v = ibase(D)[LAST];   break;
                default: v = ibase(8 + fi)[0]; break;
            }
        } else if (grp == 1) {
            switch (corner) {
                case 0:  v = 0.5f * ibase(fi)[(size_t)LAST * W_IN]
                           + 0.5f * ibase(D)[LAST];               break;
                case 1:  v = ibase(4 + A)[(size_t)LAST * W_IN];   break;
                case 2:  v = ibase(4 + D)[LAST];                  break;
                default: v = 0.5f * ibase(8 + fi)[LAST]
                           + 0.5f * ibase(8 + D)[(size_t)LAST * W_IN]; break;
            }
        } else {
            const size_t LL = (size_t)LAST * W_IN + LAST;
            switch (corner) {
                case 0:  v = ibase(fi)[LL];     break;
                case 1:  v = ibase(8 + A)[LL];  break;
                case 2:  v = ibase(8 + D)[LL];  break;
                default: v = ibase(8 + B2)[LL]; break;
            }
        }

        size_t dst;
        switch (corner) {
            case 0:  dst = 0;                                         break;
            case 1:  dst = (size_t)(W_OUT - 1);                       break;
            case 2:  dst = (size_t)(H_OUT - 1) * W_OUT;               break;
            default: dst = (size_t)(H_OUT - 1) * W_OUT + (W_OUT - 1); break;
        }
        out[(size_t)plane * PLANE_OUT + dst] = v;
        return;
    }

    // ============ copy + edge-scatter blocks, 8 floats/thread ============
    int idx = blockIdx.x * blockDim.x + threadIdx.x;   // 8-float chunk index
    int plane = idx >> 13;            // 8192 chunks per plane
    int rem   = idx & 8191;
    int i     = rem >> 5;             // 32 chunks per row
    int j8    = rem & 31;             // chunk within row (8 floats each)

    // Two back-to-back aligned 16B loads (front-batched for MLP).
    const float4* p = reinterpret_cast<const float4*>(in) + ((size_t)idx << 1);
    float4 a = p[0];
    float4 b = p[1];

    {
        float* o = out + (size_t)plane * PLANE_OUT + (size_t)(i + 1) * W_OUT + (j8 * 8 + 1);
        o[0] = a.x; o[1] = a.y; o[2] = a.z; o[3] = a.w;
        o[4] = b.x; o[5] = b.y; o[6] = b.z; o[7] = b.w;
    }

    // Fast exit for interior threads (~94%).
    if (!((i == 0) | (i == H_IN - 1) | (j8 == 0) | (j8 == 31))) return;

    const int face = plane >> 7;
    const int ch   = plane & (CH - 1);
    const int gg   = face >> 2;       // 0=north, 1=equatorial, 2=south
    const int gi   = face & 3;
    const int j    = j8 * 8;          // src column of a.x

    auto dbase = [&](int df) -> float* {
        return out + ((size_t)df * CH + ch) * PLANE_OUT;
    };
    const size_t ROW_BOT = (size_t)(H_OUT - 1) * W_OUT;   // row 257 offset
    const int    COL_R   = W_OUT - 1;                      // col 257

    // helpers to write the 8 values to a row segment or a column segment
    auto wrow = [&](float* d) {   // d points at dest col j+1 in some row
        d[0] = a.x; d[1] = a.y; d[2] = a.z; d[3] = a.w;
        d[4] = b.x; d[5] = b.y; d[6] = b.z; d[7] = b.w;
    };
    auto wcol = [&](float* d) {   // d points at dest row j+1 in some column
        d[0 * W_OUT] = a.x; d[1 * W_OUT] = a.y; d[2 * W_OUT] = a.z; d[3 * W_OUT] = a.w;
        d[4 * W_OUT] = b.x; d[5 * W_OUT] = b.y; d[6 * W_OUT] = b.z; d[7 * W_OUT] = b.w;
    };

    if (gg == 0) {                       // northern source faces 0-3
        if (i == 0)                      // -> face (gi+1)&3, col0, rows j+1..j+8
            wcol(dbase((gi + 1) & 3) + (size_t)(j + 1) * W_OUT);
        if (i == H_IN - 1)               // -> face 4+gi, row0, cols j+1..j+8
            wrow(dbase(4 + gi) + (j + 1));
        if (j8 == 0)                     // (i,0) -> face (gi+3)&3, row0 col i+1
            dbase((gi + 3) & 3)[i + 1] = a.x;
        if (j8 == 31)                    // (i,255) -> face 4+((gi+1)&3), col0 row i+1
            dbase(4 + ((gi + 1) & 3))[(size_t)(i + 1) * W_OUT] = b.w;
    } else if (gg == 1) {                // equatorial source faces 4-7
        if (i == 0)                      // -> face gi, row257, cols j+1..j+8
            wrow(dbase(gi) + ROW_BOT + (j + 1));
        if (i == H_IN - 1)               // -> face 8+((gi+3)&3), row0, cols j+1..j+8
            wrow(dbase(8 + ((gi + 3) & 3)) + (j + 1));
        if (j8 == 0)                     // (i,0) -> face (gi+3)&3, col257 row i+1
            dbase((gi + 3) & 3)[(size_t)(i + 1) * W_OUT + COL_R] = a.x;
        if (j8 == 31)                    // (i,255) -> face 8+gi, col0 row i+1
            dbase(8 + gi)[(size_t)(i + 1) * W_OUT] = b.w;
    } else {                             // southern source faces 8-11
        if (i == 0)                      // -> face 4+gi, row257, cols j+1..j+8
            wrow(dbase(4 + gi) + ROW_BOT + (j + 1));
        if (i == H_IN - 1)               // -> face 8+((gi+3)&3), col257, rows j+1..j+8
            wcol(dbase(8 + ((gi + 3) & 3)) + (size_t)(j + 1) * W_OUT + COL_R);
        if (j8 == 0)                     // (i,0) -> face 4+((gi+1)&3), col257 row i+1
            dbase(4 + ((gi + 1) & 3))[(size_t)(i + 1) * W_OUT + COL_R] = a.x;
        if (j8 == 31)                    // (i,255) -> face 8+((gi+1)&3), row257 col i+1
            dbase(8 + ((gi + 1) & 3))[ROW_BOT + i + 1] = b.w;
    }
}

extern "C" void kernel_launch(void* const* d_in, const int* in_sizes, int n_in,
                              void* d_out, int out_size) {
    const float* x = (const float*)d_in[0];
    float* out = (float*)d_out;

    const int TPB = 256;
    hp_main<<<N_COPY_BLOCKS + N_CORNER_BLOCKS, TPB>>>(x, out);

    (void)d_in; (void)in_sizes; (void)n_in; (void)out_size;
}

// round 14
// speedup vs baseline: 2.2367x; 2.2367x over previous
#include <cuda_runtime.h>
#include <cstddef>

// Problem constants: B=1, F=12, C=128, H=W=256, pad=1.
#define H_IN 256
#define W_IN 256
#define CH   128
#define H_OUT 258
#define W_OUT 258
#define PLANE_IN  (H_IN * W_IN)     // 65536
#define PLANE_OUT (H_OUT * W_OUT)   // 66564
#define N_PLANES  (12 * CH)         // 1536
// Each block: 256 threads x 2 float4 chunks = 512 chunks = 8 rows.
#define N_COPY_BLOCKS ((N_PLANES * PLANE_IN / 4) / 512)   // 49152
#define N_CORNER_BLOCKS 24          // 6144 threads: one per (plane, corner)

// ---------------------------------------------------------------------------
// Single launch, block-granularity fusion (R9 structure, proven at 146.9us).
// ILP fix over R11: each thread handles TWO lane-consecutive float4 chunks
// (base+t and base+t+256), so every LDG.128/STG stays fully coalesced
// (R11's 8-consecutive-floats-per-thread gave 32B lane strides -> 8x store
// sector amplification -> 315us). Loads front-batched for MLP_p1=2.
// ---------------------------------------------------------------------------
__global__ void hp_main(const float* __restrict__ in, float* __restrict__ out) {
    // ================= corner blocks =================
    if (blockIdx.x >= N_COPY_BLOCKS) {
        int t = (blockIdx.x - N_COPY_BLOCKS) * blockDim.x + threadIdx.x;
        if (t >= N_PLANES * 4) return;
        const int corner = t & 3;          // 0=TL 1=TR 2=BL 3=BR
        const int plane  = t >> 2;

        const int face = plane >> 7;
        const int ch   = plane & (CH - 1);
        const int grp  = face >> 2;
        const int fi   = face & 3;
        const int A  = (fi + 1) & 3;
        const int B2 = (fi + 2) & 3;
        const int D  = (fi + 3) & 3;
        const int LAST = H_IN - 1;

        auto ibase = [&](int g) -> const float* {
            return in + ((size_t)g * CH + ch) * PLANE_IN;
        };

        float v;
        if (grp == 0) {
            switch (corner) {
                case 0:  v = ibase(B2)[0];     break;
                case 1:  v = ibase(A)[0];      break;
                case 2:  v = ibase(D)[LAST];   break;
                default: v = ibase(8 + fi)[0]; break;
            }
        } else if (grp == 1) {
            switch (corner) {
                case 0:  v = 0.5f * ibase(fi)[(size_t)LAST * W_IN]
                           + 0.5f * ibase(D)[LAST];               break;
                case 1:  v = ibase(4 + A)[(size_t)LAST * W_IN];   break;
                case 2:  v = ibase(4 + D)[LAST];                  break;
                default: v = 0.5f * ibase(8 + fi)[LAST]
                           + 0.5f * ibase(8 + D)[(size_t)LAST * W_IN]; break;
            }
        } else {
            const size_t LL = (size_t)LAST * W_IN + LAST;
            switch (corner) {
                case 0:  v = ibase(fi)[LL];     break;
                case 1:  v = ibase(8 + A)[LL];  break;
                case 2:  v = ibase(8 + D)[LL];  break;
                default: v = ibase(8 + B2)[LL]; break;
            }
        }

        size_t dst;
        switch (corner) {
            case 0:  dst = 0;                                         break;
            case 1:  dst = (size_t)(W_OUT - 1);                       break;
            case 2:  dst = (size_t)(H_OUT - 1) * W_OUT;               break;
            default: dst = (size_t)(H_OUT - 1) * W_OUT + (W_OUT - 1); break;
        }
        out[(size_t)plane * PLANE_OUT + dst] = v;
        return;
    }

    // ====== copy + edge-scatter blocks: 2 coalesced chunks per thread ======
    const int idx0 = blockIdx.x * 512 + threadIdx.x;   // float4 chunk indices
    const int idx1 = idx0 + 256;

    // Front-batched loads (MLP=2), both warp-contiguous.
    float4 a = reinterpret_cast<const float4*>(in)[idx0];
    float4 b = reinterpret_cast<const float4*>(in)[idx1];

    auto process = [&](int idx, float4 v) {
        int plane = idx >> 14;            // 16384 chunks per plane
        int rem   = idx & 16383;
        int i     = rem >> 6;             // 64 chunks per row
        int j4    = rem & 63;

        {
            float* o = out + (size_t)plane * PLANE_OUT + (size_t)(i + 1) * W_OUT + (j4 * 4 + 1);
            o[0] = v.x; o[1] = v.y; o[2] = v.z; o[3] = v.w;
        }

        // Fast exit for interior chunks (~97%).
        if (!((i == 0) | (i == H_IN - 1) | (j4 == 0) | (j4 == 63))) return;

        const int face = plane >> 7;
        const int ch   = plane & (CH - 1);
        const int gg   = face >> 2;       // 0=north, 1=equatorial, 2=south
        const int gi   = face & 3;
        const int j    = j4 * 4;          // src column of v.x

        auto dbase = [&](int df) -> float* {
            return out + ((size_t)df * CH + ch) * PLANE_OUT;
        };
        const size_t ROW_BOT = (size_t)(H_OUT - 1) * W_OUT;   // row 257 offset
        const int    COL_R   = W_OUT - 1;                      // col 257

        if (gg == 0) {                       // northern source faces 0-3
            if (i == 0) {                    // -> face (gi+1)&3, col0, rows j+1..j+4
                float* d = dbase((gi + 1) & 3);
                d[(size_t)(j + 1) * W_OUT] = v.x;
                d[(size_t)(j + 2) * W_OUT] = v.y;
                d[(size_t)(j + 3) * W_OUT] = v.z;
                d[(size_t)(j + 4) * W_OUT] = v.w;
            }
            if (i == H_IN - 1) {             // -> face 4+gi, row0, cols j+1..
                float* d = dbase(4 + gi);
                d[j + 1] = v.x; d[j + 2] = v.y; d[j + 3] = v.z; d[j + 4] = v.w;
            }
            if (j4 == 0)                     // (i,0) -> face (gi+3)&3, row0 col i+1
                dbase((gi + 3) & 3)[i + 1] = v.x;
            if (j4 == 63)                    // (i,255) -> face 4+((gi+1)&3), col0 row i+1
                dbase(4 + ((gi + 1) & 3))[(size_t)(i + 1) * W_OUT] = v.w;
        } else if (gg == 1) {                // equatorial source faces 4-7
            if (i == 0) {                    // -> face gi, row257, cols j+1..
                float* d = dbase(gi) + ROW_BOT;
                d[j + 1] = v.x; d[j + 2] = v.y; d[j + 3] = v.z; d[j + 4] = v.w;
            }
            if (i == H_IN - 1) {             // -> face 8+((gi+3)&3), row0, cols j+1..
                float* d = dbase(8 + ((gi + 3) & 3));
                d[j + 1] = v.x; d[j + 2] = v.y; d[j + 3] = v.z; d[j + 4] = v.w;
            }
            if (j4 == 0)                     // (i,0) -> face (gi+3)&3, col257 row i+1
                dbase((gi + 3) & 3)[(size_t)(i + 1) * W_OUT + COL_R] = v.x;
            if (j4 == 63)                    // (i,255) -> face 8+gi, col0 row i+1
                dbase(8 + gi)[(size_t)(i + 1) * W_OUT] = v.w;
        } else {                             // southern source faces 8-11
            if (i == 0) {                    // -> face 4+gi, row257, cols j+1..
                float* d = dbase(4 + gi) + ROW_BOT;
                d[j + 1] = v.x; d[j + 2] = v.y; d[j + 3] = v.z; d[j + 4] = v.w;
            }
            if (i == H_IN - 1) {             // -> face 8+((gi+3)&3), col257, rows j+1..
                float* d = dbase(8 + ((gi + 3) & 3)) + COL_R;
                d[(size_t)(j + 1) * W_OUT] = v.x;
                d[(size_t)(j + 2) * W_OUT] = v.y;
                d[(size_t)(j + 3) * W_OUT] = v.z;
                d[(size_t)(j + 4) * W_OUT] = v.w;
            }
            if (j4 == 0)                     // (i,0) -> face 4+((gi+1)&3), col257 row i+1
                dbase(4 + ((gi + 1) & 3))[(size_t)(i + 1) * W_OUT + COL_R] = v.x;
            if (j4 == 63)                    // (i,255) -> face 8+((gi+1)&3), row257 col i+1
                dbase(8 + ((gi + 1) & 3))[ROW_BOT + i + 1] = v.w;
        }
    };

    process(idx0, a);
    process(idx1, b);
}

extern "C" void kernel_launch(void* const* d_in, const int* in_sizes, int n_in,
                              void* d_out, int out_size) {
    const float* x = (const float*)d_in[0];
    float* out = (float*)d_out;

    const int TPB = 256;
    hp_main<<<N_COPY_BLOCKS + N_CORNER_BLOCKS, TPB>>>(x, out);

    (void)d_in; (void)in_sizes; (void)n_in; (void)out_size;
}